// round 14
// baseline (speedup 1.0000x reference)
#include <cuda_runtime.h>
#include <cuda_bf16.h>
#include <math.h>

#define C_CH   128
#define HW     3136          // 56*56
#define B_SZ   64
#define NCHUNK 8
#define NTOT   (B_SZ * HW)   // 200704 elements per channel
#define HW4    (HW / 4)      // 784 float4 per plane
#define NPLANE (B_SZ * C_CH) // 8192 planes
#define GRID   1024          // 7 blocks/SM forced -> 1036 slots >= 1024
#define PPB    8             // planes per block (1 per warp)

// scratch (no device allocation allowed)
__device__ float g_pmax[NPLANE];
__device__ float g_pmin[NPLANE];
__device__ float g_psum[NPLANE];
__device__ unsigned g_count = 0;   // generation-based: never reset

__device__ __forceinline__ float qbf(float v) {
    return __bfloat162float(__float2bfloat16(v));
}

__global__ void __launch_bounds__(256, 7)
fused_kernel(const float* __restrict__ x,
             const float* __restrict__ gamma,
             const float* __restrict__ beta,
             float* __restrict__ out) {
    const int tid  = threadIdx.x;
    const int warp = tid >> 5;
    const int lane = tid & 31;
    const int p    = blockIdx.x * PPB + warp;      // this warp's plane

    // ======================= phase 1: per-plane stats =======================
    {
        const float4* px = reinterpret_cast<const float4*>(x) + (size_t)p * HW4;

        float vmax = -INFINITY, vmin = INFINITY, vsum = 0.0f;

        #define ACC4(V)                                                          \
            vmax = fmaxf(vmax, fmaxf(fmaxf((V).x, (V).y), fmaxf((V).z, (V).w))); \
            vmin = fminf(vmin, fminf(fminf((V).x, (V).y), fminf((V).z, (V).w))); \
            vsum += (qbf((V).x) + qbf((V).y)) + (qbf((V).z) + qbf((V).w));

        // 784 = 6*128 + 16 : six rounds of 4 front-batched float4 + tail
        #pragma unroll
        for (int r = 0; r < 6; ++r) {
            const int b = r * 128 + lane;
            float4 v0 = px[b];
            float4 v1 = px[b + 32];
            float4 v2 = px[b + 64];
            float4 v3 = px[b + 96];
            ACC4(v0) ACC4(v1) ACC4(v2) ACC4(v3)
        }
        if (lane < 16) {
            float4 v = px[768 + lane];
            ACC4(v)
        }
        #undef ACC4

        #pragma unroll
        for (int o = 16; o > 0; o >>= 1) {
            vmax = fmaxf(vmax, __shfl_down_sync(0xFFFFFFFFu, vmax, o));
            vmin = fminf(vmin, __shfl_down_sync(0xFFFFFFFFu, vmin, o));
            vsum +=            __shfl_down_sync(0xFFFFFFFFu, vsum, o);
        }
        if (lane == 0) {
            g_pmax[p] = vmax;   // raw; quantized at chunk level (monotonic)
            g_pmin[p] = vmin;
            g_psum[p] = vsum;
        }
    }

    // ======================= grid-wide barrier ==============================
    __syncthreads();
    if (tid == 0) {
        __threadfence();                       // publish g_p* before arriving
        unsigned old = atomicAdd(&g_count, 1u);
        unsigned target = (old / GRID + 1u) * GRID;
        for (;;) {
            unsigned v;
            asm volatile("ld.volatile.global.u32 %0, [%1];" : "=r"(v) : "l"(&g_count));
            if (v >= target) break;
            __nanosleep(64);
        }
    }
    __syncthreads();

    // ============ finalize (the block's 8 channels, coalesced) ==============
    // Block planes are blockIdx*8 .. blockIdx*8+7 -> channels c0..c0+7.
    const int c0 = (blockIdx.x * PPB) & (C_CH - 1);
    __shared__ float s_cmax[NCHUNK][PPB], s_cmin[NCHUNK][PPB], s_csum[NCHUNK][PPB];
    __shared__ float s_avg[PPB], s_scale[PPB], s_gam[PPB], s_beta[PPB];
    {
        // tid = j*8 + g : g = channel offset (0..7), j = 0..31 covers 64 b's x2
        const int g = tid & 7;
        const int j = tid >> 3;                // warp w holds j in [4w, 4w+4)
        float pm = -INFINITY, pn = INFINITY, ps = 0.0f;
        #pragma unroll
        for (int m = 0; m < 2; ++m) {
            const int idx = (j * 2 + m) * C_CH + c0 + g;   // lane-consecutive
            pm = fmaxf(pm, __ldcg(&g_pmax[idx]));
            pn = fminf(pn, __ldcg(&g_pmin[idx]));
            ps +=           __ldcg(&g_psum[idx]);
        }
        // chunk k = j>>2 = warp id; reduce the 4 j's of this chunk (lane bits 3,4)
        pm = fmaxf(pm, __shfl_xor_sync(0xFFFFFFFFu, pm, 8));
        pn = fminf(pn, __shfl_xor_sync(0xFFFFFFFFu, pn, 8));
        ps +=           __shfl_xor_sync(0xFFFFFFFFu, ps, 8);
        pm = fmaxf(pm, __shfl_xor_sync(0xFFFFFFFFu, pm, 16));
        pn = fminf(pn, __shfl_xor_sync(0xFFFFFFFFu, pn, 16));
        ps +=           __shfl_xor_sync(0xFFFFFFFFu, ps, 16);
        if (lane < 8) {
            s_cmax[warp][g] = qbf(pm);         // q(chunk max) == chunk max of q
            s_cmin[warp][g] = qbf(pn);
            s_csum[warp][g] = ps;
        }
    }
    __syncthreads();
    if (tid < PPB) {
        const int g = tid;
        float sm = 0.f, sn = 0.f, st = 0.f;
        #pragma unroll
        for (int k = 0; k < NCHUNK; ++k) {
            sm += s_cmax[k][g];
            sn += s_cmin[k][g];
            st += s_csum[k][g];
        }
        const float sum_max = qbf(sm);
        const float sum_min = qbf(sn);
        const float avg_max = qbf(sum_max / (float)NCHUNK);
        const float avg_min = qbf(sum_min / (float)NCHUNK);
        const float total   = qbf(st);

        const double chunk_size = (double)(NCHUNK * HW);  // 25088
        const float scale_fix = (float)(1.0 / sqrt(2.0 * log(chunk_size)));

        s_avg[g]   = qbf(total / (float)NTOT);
        s_scale[g] = qbf(1.0f / ((avg_max - avg_min) * scale_fix + 1e-5f));
        s_gam[g]   = qbf(gamma[c0 + g]);
        s_beta[g]  = beta[c0 + g];
    }
    __syncthreads();

    // ======================= phase 2: normalize =============================
    // Same plane this warp read in phase 1, REVERSED so the most recently
    // cached lines (L1 persists within the launch) are re-read first.
    {
        const float avg   = s_avg[warp];
        const float scale = s_scale[warp];
        const float gm    = s_gam[warp];
        const float be    = s_beta[warp];

        const float4* px = reinterpret_cast<const float4*>(x)   + (size_t)p * HW4;
        float4*       po = reinterpret_cast<float4*>(out)       + (size_t)p * HW4;

        float4 r; float t;
        #define NORM4(V, R)                                                \
            t = qbf((qbf((V).x) - avg) * scale); (R).x = qbf(t * gm + be); \
            t = qbf((qbf((V).y) - avg) * scale); (R).y = qbf(t * gm + be); \
            t = qbf((qbf((V).z) - avg) * scale); (R).z = qbf(t * gm + be); \
            t = qbf((qbf((V).w) - avg) * scale); (R).w = qbf(t * gm + be);

        if (lane < 16) {                        // tail was read last in phase 1
            float4 v = px[768 + lane];
            NORM4(v, r); __stcs(po + 768 + lane, r);
        }
        #pragma unroll
        for (int rr = 5; rr >= 0; --rr) {       // 6 rounds of 128 f4, reversed
            const int b = rr * 128 + lane;
            float4 v0 = px[b];
            float4 v1 = px[b + 32];
            float4 v2 = px[b + 64];
            float4 v3 = px[b + 96];
            NORM4(v0, r); __stcs(po + b,      r);
            NORM4(v1, r); __stcs(po + b + 32, r);
            NORM4(v2, r); __stcs(po + b + 64, r);
            NORM4(v3, r); __stcs(po + b + 96, r);
        }
        #undef NORM4
    }
}

// ---------------------------------------------------------------------------
extern "C" void kernel_launch(void* const* d_in, const int* in_sizes, int n_in,
                              void* d_out, int out_size) {
    const float* x     = (const float*)d_in[0];
    const float* gamma = (const float*)d_in[1];
    const float* beta  = (const float*)d_in[2];
    float* out = (float*)d_out;

    fused_kernel<<<GRID, 256>>>(x, gamma, beta, out);
}

// round 15
// speedup vs baseline: 2.7992x; 2.7992x over previous
#include <cuda_runtime.h>
#include <cuda_bf16.h>
#include <math.h>

#define C_CH   128
#define HW     3136          // 56*56
#define B_SZ   64
#define NCHUNK 8
#define NTOT   (B_SZ * HW)   // 200704 elements per channel
#define HW4    (HW / 4)      // 784 float4 per plane
#define HWU2   (HW / 4)      // 784 uint2 (4 bf16) per cached plane
#define CACHE_START 32       // planes b >= 32 cached in SMEM as bf16
#define SMEM_DYN (32 * HW * 2)   // 200704 bytes

__device__ __forceinline__ float qbf(float v) {
    return __bfloat162float(__float2bfloat16(v));
}

// 32B load, L2 evict_last: pin the uncached half (51.5MB chip-wide) in L2
__device__ __forceinline__ void ldg_el8(const float* p, float v[8]) {
    unsigned r0, r1, r2, r3, r4, r5, r6, r7;
    asm volatile("ld.global.L2::evict_last.v8.b32 {%0,%1,%2,%3,%4,%5,%6,%7}, [%8];"
                 : "=r"(r0), "=r"(r1), "=r"(r2), "=r"(r3),
                   "=r"(r4), "=r"(r5), "=r"(r6), "=r"(r7)
                 : "l"(p));
    v[0] = __uint_as_float(r0); v[1] = __uint_as_float(r1);
    v[2] = __uint_as_float(r2); v[3] = __uint_as_float(r3);
    v[4] = __uint_as_float(r4); v[5] = __uint_as_float(r5);
    v[6] = __uint_as_float(r6); v[7] = __uint_as_float(r7);
}

__global__ void __launch_bounds__(1024, 1)
channel_kernel(const float* __restrict__ x,
               const float* __restrict__ gamma,
               const float* __restrict__ beta,
               float* __restrict__ out) {
    extern __shared__ __nv_bfloat16 sx[];          // 32 planes x 3136 bf16
    uint2* sx2 = reinterpret_cast<uint2*>(sx);     // 4 bf16 per uint2

    __shared__ float s_pmax[B_SZ], s_pmin[B_SZ], s_psum[B_SZ];
    __shared__ float s_cmax[NCHUNK], s_cmin[NCHUNK], s_csum[NCHUNK];
    __shared__ float s_sc[4];                      // avg, scale, gamma_q, beta

    const int c    = blockIdx.x;                   // this block's channel
    const int tid  = threadIdx.x;
    const int warp = tid >> 5;                     // 0..31
    const int lane = tid & 31;

    // ===================== phase 1: stats (+ cache upper half) ==============
    #pragma unroll
    for (int half = 0; half < 2; ++half) {
        const int b = 2 * warp + half;             // batch-plane 0..63
        const float* px = x + ((size_t)b * C_CH + c) * HW;

        float vmax = -INFINITY, vmin = INFINITY, vsum = 0.0f;

        if (b < CACHE_START) {
            // lower half: pinned 32B loads, no caching
            #define ACC8(V)                                                           \
                vmax = fmaxf(vmax, fmaxf(fmaxf(fmaxf((V)[0], (V)[1]), fmaxf((V)[2], (V)[3])), \
                                         fmaxf(fmaxf((V)[4], (V)[5]), fmaxf((V)[6], (V)[7])))); \
                vmin = fminf(vmin, fminf(fminf(fminf((V)[0], (V)[1]), fminf((V)[2], (V)[3])), \
                                         fminf(fminf((V)[4], (V)[5]), fminf((V)[6], (V)[7])))); \
                vsum += ((qbf((V)[0]) + qbf((V)[1])) + (qbf((V)[2]) + qbf((V)[3])))   \
                      + ((qbf((V)[4]) + qbf((V)[5])) + (qbf((V)[6]) + qbf((V)[7])));
            #pragma unroll
            for (int g = 0; g < 3; ++g) {
                const int base = (g * 128 + lane) * 8;
                float v0[8], v1[8], v2[8], v3[8];
                ldg_el8(px + base,          v0);
                ldg_el8(px + base + 32 * 8, v1);
                ldg_el8(px + base + 64 * 8, v2);
                ldg_el8(px + base + 96 * 8, v3);
                ACC8(v0) ACC8(v1) ACC8(v2) ACC8(v3)
            }
            if (lane < 8) {
                float v[8];
                ldg_el8(px + (384 + lane) * 8, v);
                ACC8(v)
            }
            #undef ACC8
        } else {
            // upper half: streaming read, quantize to bf16, cache in SMEM
            const int slot = b - CACHE_START;
            const float4* p4 = reinterpret_cast<const float4*>(px);
            uint2* dst = sx2 + (size_t)slot * HWU2;

            #define DOQ(I)                                                        \
            {                                                                     \
                float4 v = __ldcs(p4 + (I));                                      \
                __nv_bfloat162 h0 = __floats2bfloat162_rn(v.x, v.y);              \
                __nv_bfloat162 h1 = __floats2bfloat162_rn(v.z, v.w);              \
                float2 f0 = __bfloat1622float2(h0);                               \
                float2 f1 = __bfloat1622float2(h1);                               \
                vsum += (f0.x + f0.y) + (f1.x + f1.y);                            \
                vmax = fmaxf(vmax, fmaxf(fmaxf(v.x, v.y), fmaxf(v.z, v.w)));      \
                vmin = fminf(vmin, fminf(fminf(v.x, v.y), fminf(v.z, v.w)));      \
                uint2 q;                                                          \
                q.x = *reinterpret_cast<unsigned*>(&h0);                          \
                q.y = *reinterpret_cast<unsigned*>(&h1);                          \
                dst[I] = q;                                                       \
            }
            #pragma unroll
            for (int r = 0; r < 6; ++r) {
                const int i = r * 128 + lane;
                DOQ(i) DOQ(i + 32) DOQ(i + 64) DOQ(i + 96)
            }
            if (lane < 16) DOQ(768 + lane)
            #undef DOQ
        }

        #pragma unroll
        for (int o = 16; o > 0; o >>= 1) {
            vmax = fmaxf(vmax, __shfl_down_sync(0xFFFFFFFFu, vmax, o));
            vmin = fminf(vmin, __shfl_down_sync(0xFFFFFFFFu, vmin, o));
            vsum +=            __shfl_down_sync(0xFFFFFFFFu, vsum, o);
        }
        if (lane == 0) {
            s_pmax[b] = vmax;       // raw; quantized at chunk level (monotonic)
            s_pmin[b] = vmin;
            s_psum[b] = vsum;
        }
    }
    __syncthreads();

    // ===================== finalize (in-block, one channel) =================
    if (tid < B_SZ) {
        float m = s_pmax[tid], n = s_pmin[tid], s = s_psum[tid];
        #pragma unroll
        for (int o = 1; o < 8; o <<= 1) {      // reduce 8 consecutive b's
            m = fmaxf(m, __shfl_xor_sync(0xFFFFFFFFu, m, o, 8));
            n = fminf(n, __shfl_xor_sync(0xFFFFFFFFu, n, o, 8));
            s +=         __shfl_xor_sync(0xFFFFFFFFu, s, o, 8);
        }
        if ((tid & 7) == 0) {
            const int k = tid >> 3;
            s_cmax[k] = qbf(m);                // q(chunk max) == chunk max of q
            s_cmin[k] = qbf(n);
            s_csum[k] = s;
        }
    }
    __syncthreads();
    if (tid == 0) {
        float sm = 0.f, sn = 0.f, st = 0.f;
        #pragma unroll
        for (int k = 0; k < NCHUNK; ++k) {
            sm += s_cmax[k];
            sn += s_cmin[k];
            st += s_csum[k];
        }
        const float sum_max = qbf(sm);
        const float sum_min = qbf(sn);
        const float avg_max = qbf(sum_max / (float)NCHUNK);
        const float avg_min = qbf(sum_min / (float)NCHUNK);
        const float total   = qbf(st);

        const double chunk_size = (double)(NCHUNK * HW);  // 25088
        const float scale_fix = (float)(1.0 / sqrt(2.0 * log(chunk_size)));

        s_sc[0] = qbf(total / (float)NTOT);
        s_sc[1] = qbf(1.0f / ((avg_max - avg_min) * scale_fix + 1e-5f));
        s_sc[2] = qbf(gamma[c]);
        s_sc[3] = beta[c];
    }
    __syncthreads();

    const float avg = s_sc[0], scale = s_sc[1], gm = s_sc[2], be = s_sc[3];

    // ===================== phase 2: normalize ===============================
    #pragma unroll
    for (int half = 0; half < 2; ++half) {
        const int b = 2 * warp + half;
        float4* po = reinterpret_cast<float4*>(out) + ((size_t)b * C_CH + c) * HW4;

        float4 r; float t;
        #define NORM4F(X0, X1, X2, X3, R)                              \
            t = qbf(((X0) - avg) * scale); (R).x = qbf(t * gm + be);   \
            t = qbf(((X1) - avg) * scale); (R).y = qbf(t * gm + be);   \
            t = qbf(((X2) - avg) * scale); (R).z = qbf(t * gm + be);   \
            t = qbf(((X3) - avg) * scale); (R).w = qbf(t * gm + be);

        if (b < CACHE_START) {
            // re-read the L2-pinned half; demote after use
            const float4* p4 = reinterpret_cast<const float4*>(
                x + ((size_t)b * C_CH + c) * HW);
            #define DON(I)                                                    \
            {                                                                 \
                float4 v = __ldcs(p4 + (I));                                  \
                NORM4F(qbf(v.x), qbf(v.y), qbf(v.z), qbf(v.w), r)             \
                __stcs(po + (I), r);                                          \
            }
            #pragma unroll
            for (int rr = 0; rr < 6; ++rr) {
                const int i = rr * 128 + lane;
                DON(i) DON(i + 32) DON(i + 64) DON(i + 96)
            }
            if (lane < 16) DON(768 + lane)
            #undef DON
        } else {
            // read the bf16 SMEM cache — zero L2 traffic
            const int slot = b - CACHE_START;
            const uint2* src = sx2 + (size_t)slot * HWU2;
            #define DOS(I)                                                    \
            {                                                                 \
                uint2 q = src[I];                                             \
                __nv_bfloat162 h0 = *reinterpret_cast<__nv_bfloat162*>(&q.x); \
                __nv_bfloat162 h1 = *reinterpret_cast<__nv_bfloat162*>(&q.y); \
                float2 f0 = __bfloat1622float2(h0);                           \
                float2 f1 = __bfloat1622float2(h1);                           \
                NORM4F(f0.x, f0.y, f1.x, f1.y, r)                             \
                __stcs(po + (I), r);                                          \
            }
            #pragma unroll
            for (int rr = 0; rr < 6; ++rr) {
                const int i = rr * 128 + lane;
                DOS(i) DOS(i + 32) DOS(i + 64) DOS(i + 96)
            }
            if (lane < 16) DOS(768 + lane)
            #undef DOS
        }
        #undef NORM4F
    }
}

// ---------------------------------------------------------------------------
extern "C" void kernel_launch(void* const* d_in, const int* in_sizes, int n_in,
                              void* d_out, int out_size) {
    const float* x     = (const float*)d_in[0];
    const float* gamma = (const float*)d_in[1];
    const float* beta  = (const float*)d_in[2];
    float* out = (float*)d_out;

    // idempotent; not a stream op, safe under graph capture
    cudaFuncSetAttribute(channel_kernel,
                         cudaFuncAttributeMaxDynamicSharedMemorySize, SMEM_DYN);

    channel_kernel<<<C_CH, 1024, SMEM_DYN>>>(x, gamma, beta, out);
}

// round 16
// speedup vs baseline: 3.2236x; 1.1516x over previous
#include <cuda_runtime.h>
#include <cuda_bf16.h>
#include <math.h>

#define C_CH   128
#define HW     3136          // 56*56
#define B_SZ   64
#define NCHUNK 8
#define NTOT   (B_SZ * HW)   // 200704 elements per channel
#define HW4    (HW / 4)      // 784 float4 per plane
#define NPLANE (B_SZ * C_CH) // 8192 planes
#define GRID   512           // 4 blocks/SM x 148 = 592 >= 512 (80 spare slots)
#define NTHR   512           // 16 warps -> 64 warps/SM at occ 4
#define PPB    16            // planes per block (1 per warp)

// scratch (no device allocation allowed)
__device__ float g_pmax[NPLANE];
__device__ float g_pmin[NPLANE];
__device__ float g_psum[NPLANE];
__device__ unsigned g_count = 0;   // generation-based: never reset

__device__ __forceinline__ float qbf(float v) {
    return __bfloat162float(__float2bfloat16(v));
}

__global__ void __launch_bounds__(NTHR, 4)
fused_kernel(const float* __restrict__ x,
             const float* __restrict__ gamma,
             const float* __restrict__ beta,
             float* __restrict__ out) {
    const int tid  = threadIdx.x;
    const int warp = tid >> 5;                     // 0..15
    const int lane = tid & 31;
    const int p    = blockIdx.x * PPB + warp;      // this warp's plane
    const int c0   = (blockIdx.x * PPB) & (C_CH - 1);  // block's first channel

    // ======================= phase 1: per-plane stats =======================
    {
        const float4* px = reinterpret_cast<const float4*>(x) + (size_t)p * HW4;

        float vmax = -INFINITY, vmin = INFINITY, vsum = 0.0f;

        #define ACC4(V)                                                          \
            vmax = fmaxf(vmax, fmaxf(fmaxf((V).x, (V).y), fmaxf((V).z, (V).w))); \
            vmin = fminf(vmin, fminf(fminf((V).x, (V).y), fminf((V).z, (V).w))); \
            vsum += (qbf((V).x) + qbf((V).y)) + (qbf((V).z) + qbf((V).w));

        // 784 = 6*128 + 16 : six rounds of 4 front-batched float4 + tail.
        // Default policy: lines land in L1 (persists within launch) and L2
        // (x = 103MB fits the 126MB L2 at the barrier).
        #pragma unroll
        for (int r = 0; r < 6; ++r) {
            const int b = r * 128 + lane;
            float4 v0 = px[b];
            float4 v1 = px[b + 32];
            float4 v2 = px[b + 64];
            float4 v3 = px[b + 96];
            ACC4(v0) ACC4(v1) ACC4(v2) ACC4(v3)
        }
        if (lane < 16) {
            float4 v = px[768 + lane];
            ACC4(v)
        }
        #undef ACC4

        #pragma unroll
        for (int o = 16; o > 0; o >>= 1) {
            vmax = fmaxf(vmax, __shfl_down_sync(0xFFFFFFFFu, vmax, o));
            vmin = fminf(vmin, __shfl_down_sync(0xFFFFFFFFu, vmin, o));
            vsum +=            __shfl_down_sync(0xFFFFFFFFu, vsum, o);
        }
        if (lane == 0) {
            g_pmax[p] = vmax;   // raw; quantized at chunk level (monotonic)
            g_pmin[p] = vmin;
            g_psum[p] = vsum;
        }
    }

    // ======================= grid-wide barrier ==============================
    // Generation counting (no reset across graph replays). GRID=512 at forced
    // occupancy 4 -> co-residency guaranteed with 80 spare slots.
    __syncthreads();
    if (tid == 0) {
        __threadfence();                       // publish g_p* before arriving
        unsigned old = atomicAdd(&g_count, 1u);
        unsigned target = (old / GRID + 1u) * GRID;
        for (;;) {
            unsigned v;
            asm volatile("ld.volatile.global.u32 %0, [%1];" : "=r"(v) : "l"(&g_count));
            if (v >= target) break;
            __nanosleep(64);
        }
    }
    __syncthreads();

    // ============ finalize (the block's 16 channels, coalesced) =============
    __shared__ float sp_max[32][PPB], sp_min[32][PPB], sp_sum[32][PPB];
    __shared__ float s_cmax[NCHUNK][PPB], s_cmin[NCHUNK][PPB], s_csum[NCHUNK][PPB];
    __shared__ float s_avg[PPB], s_scale[PPB], s_gam[PPB], s_beta[PPB];
    {
        // step 1: 512 threads, each combines 2 batch-planes of one channel.
        // consecutive tid -> consecutive channel -> coalesced 64B segments.
        const int g = tid & 15;                // channel offset 0..15
        const int j = tid >> 4;                // 0..31 (pair of batches)
        const int i0 = (2 * j    ) * C_CH + c0 + g;
        const int i1 = (2 * j + 1) * C_CH + c0 + g;
        sp_max[j][g] = fmaxf(__ldcg(&g_pmax[i0]), __ldcg(&g_pmax[i1]));
        sp_min[j][g] = fminf(__ldcg(&g_pmin[i0]), __ldcg(&g_pmin[i1]));
        sp_sum[j][g] =       __ldcg(&g_psum[i0]) + __ldcg(&g_psum[i1]);
    }
    __syncthreads();
    if (tid < 128) {
        // step 2: chunk k combines its 4 staged pairs
        const int g = tid & 15;
        const int k = tid >> 4;                // chunk 0..7
        float m = sp_max[4 * k][g], n = sp_min[4 * k][g], s = sp_sum[4 * k][g];
        #pragma unroll
        for (int i = 1; i < 4; ++i) {
            m = fmaxf(m, sp_max[4 * k + i][g]);
            n = fminf(n, sp_min[4 * k + i][g]);
            s +=         sp_sum[4 * k + i][g];
        }
        s_cmax[k][g] = qbf(m);                 // q(chunk max) == chunk max of q
        s_cmin[k][g] = qbf(n);
        s_csum[k][g] = s;
    }
    __syncthreads();
    if (tid < PPB) {
        const int g = tid;
        float sm = 0.f, sn = 0.f, st = 0.f;
        #pragma unroll
        for (int k = 0; k < NCHUNK; ++k) {
            sm += s_cmax[k][g];
            sn += s_cmin[k][g];
            st += s_csum[k][g];
        }
        const float sum_max = qbf(sm);
        const float sum_min = qbf(sn);
        const float avg_max = qbf(sum_max / (float)NCHUNK);
        const float avg_min = qbf(sum_min / (float)NCHUNK);
        const float total   = qbf(st);

        const double chunk_size = (double)(NCHUNK * HW);  // 25088
        const float scale_fix = (float)(1.0 / sqrt(2.0 * log(chunk_size)));

        s_avg[g]   = qbf(total / (float)NTOT);
        s_scale[g] = qbf(1.0f / ((avg_max - avg_min) * scale_fix + 1e-5f));
        s_gam[g]   = qbf(gamma[c0 + g]);
        s_beta[g]  = beta[c0 + g];
    }
    __syncthreads();

    // ======================= phase 2: normalize =============================
    // Same plane this warp read in phase 1, REVERSED so the most recently
    // cached lines (L1 persists within the launch) are re-read first.
    {
        const float avg   = s_avg[warp];
        const float scale = s_scale[warp];
        const float gm    = s_gam[warp];
        const float be    = s_beta[warp];

        const float4* px = reinterpret_cast<const float4*>(x)   + (size_t)p * HW4;
        float4*       po = reinterpret_cast<float4*>(out)       + (size_t)p * HW4;

        float4 r; float t;
        #define NORM4(V, R)                                                \
            t = qbf((qbf((V).x) - avg) * scale); (R).x = qbf(t * gm + be); \
            t = qbf((qbf((V).y) - avg) * scale); (R).y = qbf(t * gm + be); \
            t = qbf((qbf((V).z) - avg) * scale); (R).z = qbf(t * gm + be); \
            t = qbf((qbf((V).w) - avg) * scale); (R).w = qbf(t * gm + be);

        if (lane < 16) {                        // tail was read last in phase 1
            float4 v = __ldcs(px + 768 + lane);
            NORM4(v, r); __stcs(po + 768 + lane, r);
        }
        #pragma unroll
        for (int rr = 5; rr >= 0; --rr) {       // 6 rounds of 128 f4, reversed
            const int b = rr * 128 + lane;
            float4 v0 = __ldcs(px + b);
            float4 v1 = __ldcs(px + b + 32);
            float4 v2 = __ldcs(px + b + 64);
            float4 v3 = __ldcs(px + b + 96);
            NORM4(v0, r); __stcs(po + b,      r);
            NORM4(v1, r); __stcs(po + b + 32, r);
            NORM4(v2, r); __stcs(po + b + 64, r);
            NORM4(v3, r); __stcs(po + b + 96, r);
        }
        #undef NORM4
    }
}

// ---------------------------------------------------------------------------
extern "C" void kernel_launch(void* const* d_in, const int* in_sizes, int n_in,
                              void* d_out, int out_size) {
    const float* x     = (const float*)d_in[0];
    const float* gamma = (const float*)d_in[1];
    const float* beta  = (const float*)d_in[2];
    float* out = (float*)d_out;

    fused_kernel<<<GRID, NTHR>>>(x, gamma, beta, out);
}